// round 2
// baseline (speedup 1.0000x reference)
#include <cuda_runtime.h>

// Problem constants
#define NROWS 32768      // B*H*W
#define DDIM  64
#define KCB   1024
#define MT    128        // rows per CTA
#define NT    128        // codebook entries per k-tile
#define NKT   (KCB / NT) // 8 k-tiles
#define NTHREADS 256

// Output layout (float32, concatenated in reference return order)
#define OFF_ZQ    0
#define OFF_LOSS  2097152
#define OFF_PERP  2097153
#define OFF_IDX   2097154
#define OFF_DIST  2129922
// total = 35684354

// Scratch (allocation-free rule: device globals)
__device__ float        g_loss;
__device__ unsigned int g_counts[KCB];

__global__ void vq_init_kernel() {
    int t = threadIdx.x;
    if (t < KCB) g_counts[t] = 0u;
    if (t == 0) g_loss = 0.0f;
}

// smem layout (floats):
//   f_s  [64][128]  : 8192   (f tile, d-major)
//   e_s  [64][128]  : 8192   (e tile, d-major)
//   f2_s [128]      : 128
//   e2_s [128]      : 128
//   idx_s[128] (int): 128
//   red  [256]      : 256
// total 17024 floats = 68096 bytes
#define SMEM_FLOATS 17024

__global__ void __launch_bounds__(NTHREADS, 2)
vq_main_kernel(const float* __restrict__ z_e,
               const float* __restrict__ emb,
               float* __restrict__ zq_out,
               float* __restrict__ idx_out,
               float* __restrict__ dist_out)
{
    extern __shared__ float smem[];
    float* f_s  = smem;                 // [64][128]
    float* e_s  = smem + 8192;          // [64][128]
    float* f2_s = smem + 16384;         // [128]
    float* e2_s = f2_s + 128;           // [128]
    int*   idx_s = (int*)(e2_s + 128);  // [128]
    float* red  = (float*)(idx_s + 128);// [256]

    const int t  = threadIdx.x;
    const int tx = t & 15;              // k direction (16)
    const int ty = t >> 4;              // m direction (16)

    const int n0  = blockIdx.x * MT;    // first row of this CTA
    const int b   = n0 >> 10;           // batch (1024 rows per batch)
    const int hw0 = n0 & 1023;          // h*W + w offset within batch

    const float* zbase = z_e + (size_t)b * (DDIM * 1024) + hw0;

    // ---- load f tile: f_s[d][m] = z_e[b, d, hw0+m] (coalesced float4) ----
    #pragma unroll
    for (int it = 0; it < 8; ++it) {
        int li = it * NTHREADS + t;     // 0..2047
        int d  = li >> 5;               // 0..63
        int m4 = li & 31;               // float4 index along m
        float4 v = *(const float4*)(zbase + (size_t)d * 1024 + m4 * 4);
        *(float4*)(f_s + d * 128 + m4 * 4) = v;
    }
    __syncthreads();

    // ---- f2 per row ----
    if (t < 128) {
        float s = 0.0f;
        #pragma unroll
        for (int d = 0; d < DDIM; ++d) {
            float v = f_s[d * 128 + t];
            s = fmaf(v, v, s);
        }
        f2_s[t] = s;
    }

    // ---- running argmin state (8 rows per thread) ----
    float bestv[8];
    int   besti[8];
    #pragma unroll
    for (int i = 0; i < 8; ++i) { bestv[i] = 3.0e38f; besti[i] = 0; }

    // ---- loop over the 8 codebook tiles ----
    #pragma unroll 1
    for (int kt = 0; kt < NKT; ++kt) {
        const int k0 = kt * NT;
        __syncthreads();  // protect e_s / e2_s reuse

        // load e tile: e_s[d][kk] = emb[k0+kk][d]
        #pragma unroll
        for (int it = 0; it < 8; ++it) {
            int li = it * NTHREADS + t;   // 0..2047
            int kk = li & 127;
            int dc = li >> 7;             // 0..15 float4-chunk along d
            float4 v = *(const float4*)(emb + (size_t)(k0 + kk) * DDIM + dc * 4);
            e_s[(dc * 4 + 0) * 128 + kk] = v.x;
            e_s[(dc * 4 + 1) * 128 + kk] = v.y;
            e_s[(dc * 4 + 2) * 128 + kk] = v.z;
            e_s[(dc * 4 + 3) * 128 + kk] = v.w;
        }
        __syncthreads();

        if (t < 128) {
            float s = 0.0f;
            #pragma unroll
            for (int d = 0; d < DDIM; ++d) {
                float v = e_s[d * 128 + t];
                s = fmaf(v, v, s);
            }
            e2_s[t] = s;
        }
        __syncthreads();

        // 8x8 register microtile GEMM over d
        float acc[8][8];
        #pragma unroll
        for (int i = 0; i < 8; ++i)
            #pragma unroll
            for (int j = 0; j < 8; ++j)
                acc[i][j] = 0.0f;

        #pragma unroll 4
        for (int d = 0; d < DDIM; ++d) {
            float4 fa = *(float4*)(f_s + d * 128 + ty * 8);
            float4 fb = *(float4*)(f_s + d * 128 + ty * 8 + 4);
            float4 ea = *(float4*)(e_s + d * 128 + tx * 8);
            float4 eb = *(float4*)(e_s + d * 128 + tx * 8 + 4);
            float fr[8] = {fa.x, fa.y, fa.z, fa.w, fb.x, fb.y, fb.z, fb.w};
            float er[8] = {ea.x, ea.y, ea.z, ea.w, eb.x, eb.y, eb.z, eb.w};
            #pragma unroll
            for (int i = 0; i < 8; ++i)
                #pragma unroll
                for (int j = 0; j < 8; ++j)
                    acc[i][j] = fmaf(fr[i], er[j], acc[i][j]);
        }

        // epilogue: distances + argmin update + store
        #pragma unroll
        for (int i = 0; i < 8; ++i) {
            const int m  = ty * 8 + i;
            const float f2 = f2_s[m];
            float w[8];
            #pragma unroll
            for (int j = 0; j < 8; ++j) {
                const int k = k0 + tx * 8 + j;
                float v = fmaf(-2.0f, acc[i][j], f2 + e2_s[tx * 8 + j]);
                w[j] = v;
                if (v < bestv[i]) { bestv[i] = v; besti[i] = k; }
            }
            // dist segment is only 8B-aligned in the output buffer -> float2 stores
            float* drow = dist_out + (size_t)(n0 + m) * KCB + k0 + tx * 8;
            *(float2*)(drow + 0) = make_float2(w[0], w[1]);
            *(float2*)(drow + 2) = make_float2(w[2], w[3]);
            *(float2*)(drow + 4) = make_float2(w[4], w[5]);
            *(float2*)(drow + 6) = make_float2(w[6], w[7]);
        }
    }

    // ---- argmin reduction across the 16 tx lanes (shfl width 16) ----
    const unsigned mask = 0xffffffffu;
    #pragma unroll
    for (int i = 0; i < 8; ++i) {
        float v  = bestv[i];
        int   bi = besti[i];
        #pragma unroll
        for (int off = 8; off > 0; off >>= 1) {
            float ov = __shfl_down_sync(mask, v,  off, 16);
            int   oi = __shfl_down_sync(mask, bi, off, 16);
            if (ov < v || (ov == v && oi < bi)) { v = ov; bi = oi; }
        }
        if (tx == 0) idx_s[ty * 8 + i] = bi;
    }
    __syncthreads();

    // ---- index output + histogram ----
    if (t < 128) {
        int bi = idx_s[t];
        idx_out[n0 + t] = (float)bi;
        atomicAdd(&g_counts[bi], 1u);
    }

    // ---- z_q gather/scatter + loss partial ----
    float lsum = 0.0f;
    float* zq_base = zq_out + (size_t)b * (DDIM * 1024) + hw0;
    #pragma unroll 4
    for (int it = 0; it < 32; ++it) {
        int li = it * NTHREADS + t;  // 0..8191
        int d  = li >> 7;            // 0..63
        int m  = li & 127;
        float v  = emb[(size_t)idx_s[m] * DDIM + d];
        float fv = f_s[d * 128 + m];
        float df = v - fv;
        lsum = fmaf(df, df, lsum);
        zq_base[(size_t)d * 1024 + m] = v;
    }
    red[t] = lsum;
    __syncthreads();
    #pragma unroll
    for (int s = 128; s > 0; s >>= 1) {
        if (t < s) red[t] += red[t + s];
        __syncthreads();
    }
    if (t == 0) atomicAdd(&g_loss, red[0]);
}

__global__ void vq_finalize_kernel(float* __restrict__ loss_out,
                                   float* __restrict__ perp_out)
{
    __shared__ float red[KCB];
    int t = threadIdx.x;
    float c = (float)g_counts[t];
    float p = c * (1.0f / (float)NROWS);
    red[t] = p * logf(p + 1e-10f);
    __syncthreads();
    #pragma unroll
    for (int s = KCB / 2; s > 0; s >>= 1) {
        if (t < s) red[t] += red[t + s];
        __syncthreads();
    }
    if (t == 0) {
        *perp_out = expf(-red[0]);
        // codebook_loss == commitment_loss in value -> 1.25 * MSE
        *loss_out = g_loss * (1.25f / (float)(NROWS * DDIM));
    }
}

extern "C" void kernel_launch(void* const* d_in, const int* in_sizes, int n_in,
                              void* d_out, int out_size)
{
    const float* z_e = (const float*)d_in[0];
    const float* emb = (const float*)d_in[1];
    float* out = (float*)d_out;

    float* zq   = out + OFF_ZQ;
    float* loss = out + OFF_LOSS;
    float* perp = out + OFF_PERP;
    float* idxf = out + OFF_IDX;
    float* dist = out + OFF_DIST;

    // idempotent, not an allocation; safe to call every launch
    cudaFuncSetAttribute(vq_main_kernel,
                         cudaFuncAttributeMaxDynamicSharedMemorySize,
                         SMEM_FLOATS * sizeof(float));

    vq_init_kernel<<<1, 1024>>>();
    vq_main_kernel<<<NROWS / MT, NTHREADS, SMEM_FLOATS * sizeof(float)>>>(
        z_e, emb, zq, idxf, dist);
    vq_finalize_kernel<<<1, KCB>>>(loss, perp);
}

// round 4
// speedup vs baseline: 1.7443x; 1.7443x over previous
#include <cuda_runtime.h>
#include <cuda_fp16.h>

#define NROWS 32768
#define DDIM  64
#define KCB   1024
#define MT    128
#define NTILES 8
#define NTHREADS 256

#define O_ZQ    0
#define O_LOSS  2097152
#define O_PERP  2097153
#define O_IDX   2097154
#define O_DIST  2129922

// K layout: 192 used halves ([h1|h2|h1] vs [g1|g1|g2]), pitch 200 halves (400 B)
#define KP 200
#define TILE_BYTES (128 * KP * 2)   // 51200 per 128-code tile

// smem byte offsets
#define S_A    0                     // 128 x 200 halves = 51200
#define S_B0   51200                 // 51200
#define S_B1   102400                // 51200
#define S_FS   153600                // f tile [64][128] f32 = 32768
#define S_F2   186368                // 128 f32
#define S_E2   186880                // 1024 f32
#define S_AV0  190976
#define S_AI0  191488
#define S_AV1  192000
#define S_AI1  192512
#define S_IDX  193024
#define S_RED  193536                // 256 f32
#define SMEM_BYTES 194560

#define ESCALE 1024.0f
#define DSCALE (-2.0f / 1024.0f)     // exact power of two

__device__ float         g_loss;
__device__ unsigned int  g_counts[KCB];
__device__ float         g_e2[KCB];
__device__ __align__(16) unsigned char g_epack[NTILES * TILE_BYTES];

__device__ __forceinline__ unsigned smem_u32(const void* p) {
    unsigned a;
    asm("{ .reg .u64 t; cvta.to.shared.u64 t, %1; cvt.u32.u64 %0, t; }"
        : "=r"(a) : "l"(p));
    return a;
}
__device__ __forceinline__ void cp16(unsigned dst, const void* src) {
    asm volatile("cp.async.cg.shared.global [%0], [%1], 16;" :: "r"(dst), "l"(src));
}
#define CP_COMMIT() asm volatile("cp.async.commit_group;" ::: "memory")
#define CP_WAIT0()  asm volatile("cp.async.wait_group 0;"  ::: "memory")

__device__ __forceinline__ void mma16816(float* c, const unsigned* a,
                                         unsigned b0, unsigned b1) {
    asm volatile(
        "mma.sync.aligned.m16n8k16.row.col.f32.f16.f16.f32 "
        "{%0,%1,%2,%3}, {%4,%5,%6,%7}, {%8,%9}, {%0,%1,%2,%3};"
        : "+f"(c[0]), "+f"(c[1]), "+f"(c[2]), "+f"(c[3])
        : "r"(a[0]), "r"(a[1]), "r"(a[2]), "r"(a[3]), "r"(b0), "r"(b1));
}

__device__ __forceinline__ void split2(float x, __half& a, __half& b) {
    a = __float2half_rn(x);
    b = __float2half_rn(x - __half2float(a));
}

// ---- prepack: codebook -> fp16 split [g1|g1|g2] in g_epack, e2; + zero scratch ----
__global__ void vq_prepack_kernel(const float* __restrict__ emb) {
    const int t = threadIdx.x;
    if (blockIdx.x == NTILES) {
        for (int i = t; i < KCB; i += NTHREADS) g_counts[i] = 0u;
        if (t == 0) g_loss = 0.0f;
        return;
    }
    const int nt = blockIdx.x, kk = t >> 1, hf = t & 1;
    const int k = nt * 128 + kk;
    const float* ep = emb + (size_t)k * DDIM + hf * 32;
    __half* row = (__half*)(g_epack + (size_t)nt * TILE_BYTES + kk * (KP * 2));
    float e2p = 0.0f;
    #pragma unroll
    for (int i = 0; i < 32; i += 2) {
        float x0 = ep[i], x1 = ep[i + 1];
        e2p = fmaf(x0, x0, e2p);
        e2p = fmaf(x1, x1, e2p);
        __half a0, b0, a1, b1;
        split2(x0 * ESCALE, a0, b0);
        split2(x1 * ESCALE, a1, b1);
        int d = hf * 32 + i;
        *(__half2*)(row + d)       = __halves2half2(a0, a1);   // g1
        *(__half2*)(row + 64 + d)  = __halves2half2(a0, a1);   // g1 (dup)
        *(__half2*)(row + 128 + d) = __halves2half2(b0, b1);   // g2
    }
    float oth = __shfl_xor_sync(0xffffffffu, e2p, 1);
    if (hf == 0) g_e2[k] = e2p + oth;
}

__global__ void __launch_bounds__(NTHREADS, 1)
vq_main_kernel(const float* __restrict__ z_e,
               const float* __restrict__ emb,
               float* __restrict__ zq_out,
               float* __restrict__ idx_out,
               float* __restrict__ dist_out)
{
    extern __shared__ unsigned char smem[];
    const unsigned sbase = smem_u32(smem);
    const int t = threadIdx.x, lane = t & 31, w = t >> 5;
    const int wm = w & 3, wn = w >> 2;          // warp m-quad, n-half
    const int q = lane & 3, lg = lane >> 2;     // quad col, lane group (8)

    const int n0 = blockIdx.x * MT, b = n0 >> 10, hw0 = n0 & 1023;
    const float* zbase = z_e + (size_t)b * (DDIM * 1024) + hw0;

    __half* A_s  = (__half*)(smem + S_A);
    float*  f_s  = (float*)(smem + S_FS);
    float*  f2_s = (float*)(smem + S_F2);
    float*  e2_s = (float*)(smem + S_E2);
    int*    idx_s = (int*)(smem + S_IDX);
    float*  red  = (float*)(smem + S_RED);

    // prefetch B tile 0
    #pragma unroll
    for (int i = 0; i < 13; ++i) {
        int c = i * NTHREADS + t;
        if (c < TILE_BYTES / 16) cp16(sbase + S_B0 + c * 16, g_epack + c * 16);
    }
    CP_COMMIT();

    // load f tile coalesced: f_s[d][m]
    #pragma unroll
    for (int it = 0; it < 8; ++it) {
        int li = it * NTHREADS + t, d = li >> 5, m4 = li & 31;
        float4 v = *(const float4*)(zbase + (size_t)d * 1024 + m4 * 4);
        *(float4*)(f_s + d * 128 + m4 * 4) = v;
    }
    #pragma unroll
    for (int i = 0; i < 4; ++i) e2_s[i * NTHREADS + t] = g_e2[i * NTHREADS + t];
    __syncthreads();

    // f2 per row (serial d, matches reference-class ordering)
    if (t < 128) {
        float s = 0.0f;
        #pragma unroll
        for (int d = 0; d < DDIM; ++d) { float v = f_s[d * 128 + t]; s = fmaf(v, v, s); }
        f2_s[t] = s;
    }

    // build A = [h1 | h2 | h1] fp16, row pitch KP
    {
        const int m = t >> 1, hf = t & 1;
        __half* arow = A_s + m * KP;
        #pragma unroll
        for (int i = 0; i < 32; i += 2) {
            int d = hf * 32 + i;
            float x0 = f_s[d * 128 + m], x1 = f_s[(d + 1) * 128 + m];
            __half a0, b0, a1, b1;
            split2(x0, a0, b0);
            split2(x1, a1, b1);
            *(__half2*)(arow + d)       = __halves2half2(a0, a1);
            *(__half2*)(arow + 64 + d)  = __halves2half2(b0, b1);
            *(__half2*)(arow + 128 + d) = __halves2half2(a0, a1);
        }
    }
    __syncthreads();

    float bestv[4];
    int   besti[4];
    #pragma unroll
    for (int i = 0; i < 4; ++i) { bestv[i] = 3.0e38f; besti[i] = 0; }

    #pragma unroll 1
    for (int t8 = 0; t8 < NTILES; ++t8) {
        CP_WAIT0();
        __syncthreads();
        if (t8 < NTILES - 1) {
            const unsigned char* src = g_epack + (size_t)(t8 + 1) * TILE_BYTES;
            unsigned dstb = sbase + (((t8 + 1) & 1) ? S_B1 : S_B0);
            #pragma unroll
            for (int i = 0; i < 13; ++i) {
                int c = i * NTHREADS + t;
                if (c < TILE_BYTES / 16) cp16(dstb + c * 16, src + c * 16);
            }
            CP_COMMIT();
        }
        const __half* B_s = (const __half*)(smem + ((t8 & 1) ? S_B1 : S_B0));

        float C[2][8][4];
        #pragma unroll
        for (int mt = 0; mt < 2; ++mt)
            #pragma unroll
            for (int nt = 0; nt < 8; ++nt)
                #pragma unroll
                for (int r = 0; r < 4; ++r) C[mt][nt][r] = 0.0f;

        #pragma unroll
        for (int kt = 0; kt < 12; ++kt) {
            const int k0 = kt * 16 + 2 * q;
            unsigned a[2][4];
            #pragma unroll
            for (int mt = 0; mt < 2; ++mt) {
                const int r = wm * 32 + mt * 16 + lg;
                a[mt][0] = *(const unsigned*)(A_s + r * KP + k0);
                a[mt][1] = *(const unsigned*)(A_s + (r + 8) * KP + k0);
                a[mt][2] = *(const unsigned*)(A_s + r * KP + k0 + 8);
                a[mt][3] = *(const unsigned*)(A_s + (r + 8) * KP + k0 + 8);
            }
            #pragma unroll
            for (int nt = 0; nt < 8; ++nt) {
                const int n = wn * 64 + nt * 8 + lg;
                unsigned b0 = *(const unsigned*)(B_s + n * KP + k0);
                unsigned b1 = *(const unsigned*)(B_s + n * KP + k0 + 8);
                mma16816(C[0][nt], a[0], b0, b1);
                mma16816(C[1][nt], a[1], b0, b1);
            }
        }

        // epilogue: distances, argmin, direct float2 stores
        #pragma unroll
        for (int mt = 0; mt < 2; ++mt) {
            const int r = wm * 32 + mt * 16 + lg;
            const float f2a = f2_s[r], f2b = f2_s[r + 8];
            float* dra = dist_out + (size_t)(n0 + r) * KCB;
            float* drb = dist_out + (size_t)(n0 + r + 8) * KCB;
            #pragma unroll
            for (int nt = 0; nt < 8; ++nt) {
                const int col = t8 * 128 + wn * 64 + nt * 8 + 2 * q;
                const float e2x = e2_s[col], e2y = e2_s[col + 1];
                float d0 = fmaf(DSCALE, C[mt][nt][0], f2a + e2x);
                float d1 = fmaf(DSCALE, C[mt][nt][1], f2a + e2y);
                float d2 = fmaf(DSCALE, C[mt][nt][2], f2b + e2x);
                float d3 = fmaf(DSCALE, C[mt][nt][3], f2b + e2y);
                if (d0 < bestv[mt * 2])     { bestv[mt * 2] = d0;     besti[mt * 2] = col; }
                if (d1 < bestv[mt * 2])     { bestv[mt * 2] = d1;     besti[mt * 2] = col + 1; }
                if (d2 < bestv[mt * 2 + 1]) { bestv[mt * 2 + 1] = d2; besti[mt * 2 + 1] = col; }
                if (d3 < bestv[mt * 2 + 1]) { bestv[mt * 2 + 1] = d3; besti[mt * 2 + 1] = col + 1; }
                *(float2*)(dra + col) = make_float2(d0, d1);
                *(float2*)(drb + col) = make_float2(d2, d3);
            }
        }
        __syncthreads();
    }

    // quad argmin reduction (lanes sharing a row), tie -> lowest index
    #pragma unroll
    for (int i = 0; i < 4; ++i) {
        float v = bestv[i];
        int  bi = besti[i];
        #pragma unroll
        for (int off = 2; off > 0; off >>= 1) {
            float ov = __shfl_down_sync(0xffffffffu, v, off, 4);
            int   oi = __shfl_down_sync(0xffffffffu, bi, off, 4);
            if (ov < v || (ov == v && oi < bi)) { v = ov; bi = oi; }
        }
        if (q == 0) {
            const int r = wm * 32 + (i >> 1) * 16 + (i & 1) * 8 + lg;
            ((float*)(smem + (wn ? S_AV1 : S_AV0)))[r] = v;
            ((int*)  (smem + (wn ? S_AI1 : S_AI0)))[r] = bi;
        }
    }
    __syncthreads();

    if (t < 128) {
        float v0 = ((float*)(smem + S_AV0))[t], v1 = ((float*)(smem + S_AV1))[t];
        int   i0 = ((int*)(smem + S_AI0))[t],   i1 = ((int*)(smem + S_AI1))[t];
        int bi = (v1 < v0 || (v1 == v0 && i1 < i0)) ? i1 : i0;
        idx_s[t] = bi;
        idx_out[n0 + t] = (float)bi;
        atomicAdd(&g_counts[bi], 1u);
    }
    __syncthreads();

    // z_q gather/scatter + loss partial
    float lsum = 0.0f;
    float* zq_base = zq_out + (size_t)b * (DDIM * 1024) + hw0;
    #pragma unroll 4
    for (int it = 0; it < 32; ++it) {
        int li = it * NTHREADS + t, d = li >> 7, m = li & 127;
        float v  = emb[(size_t)idx_s[m] * DDIM + d];
        float fv = f_s[d * 128 + m];
        float df = v - fv;
        lsum = fmaf(df, df, lsum);
        zq_base[(size_t)d * 1024 + m] = v;
    }
    red[t] = lsum;
    __syncthreads();
    #pragma unroll
    for (int s = 128; s > 0; s >>= 1) {
        if (t < s) red[t] += red[t + s];
        __syncthreads();
    }
    if (t == 0) atomicAdd(&g_loss, red[0]);
}

__global__ void vq_finalize_kernel(float* __restrict__ loss_out,
                                   float* __restrict__ perp_out)
{
    __shared__ float red[KCB];
    int t = threadIdx.x;
    float c = (float)g_counts[t];
    float p = c * (1.0f / (float)NROWS);
    red[t] = p * logf(p + 1e-10f);
    __syncthreads();
    #pragma unroll
    for (int s = KCB / 2; s > 0; s >>= 1) {
        if (t < s) red[t] += red[t + s];
        __syncthreads();
    }
    if (t == 0) {
        *perp_out = expf(-red[0]);
        *loss_out = g_loss * (1.25f / (float)(NROWS * DDIM));
    }
}

extern "C" void kernel_launch(void* const* d_in, const int* in_sizes, int n_in,
                              void* d_out, int out_size)
{
    const float* z_e = (const float*)d_in[0];
    const float* emb = (const float*)d_in[1];
    float* out = (float*)d_out;

    cudaFuncSetAttribute(vq_main_kernel,
                         cudaFuncAttributeMaxDynamicSharedMemorySize, SMEM_BYTES);

    vq_prepack_kernel<<<NTILES + 1, NTHREADS>>>(emb);
    vq_main_kernel<<<NROWS / MT, NTHREADS, SMEM_BYTES>>>(
        z_e, emb, out + O_ZQ, out + O_IDX, out + O_DIST);
    vq_finalize_kernel<<<1, KCB>>>(out + O_LOSS, out + O_PERP);
}